// round 1
// baseline (speedup 1.0000x reference)
#include <cuda_runtime.h>

// Sparse MoE FFN: T=8192 tokens, H=1024 hidden, E=8 experts, top-2 routing.
// out[t,h] = sum_{k in top2(t)} w_k * ( x[t,:] . W_experts[h*E+e_k, :] + b_experts[h*E+e_k] )
// with w_k = 2-way softmax over the top-2 gate logits.

#define NTOK 8192
#define HDIM 1024
#define NEXP 8

#define BM 64
#define BN 64
#define BK 16

// Routing scratch (device globals: no allocations allowed in kernel_launch).
__device__ int   g_cnt[NEXP];
__device__ int   g_tok[NEXP][NTOK];
__device__ float g_wt [NEXP][NTOK];

__global__ void zero_counts_kernel() {
    if (threadIdx.x < NEXP) g_cnt[threadIdx.x] = 0;
}

// One warp per token: 8 gate logits, top-2, renormalized weights, append to
// per-expert lists. List order is nondeterministic but output is order-invariant.
__global__ __launch_bounds__(256) void gate_kernel(
        const float* __restrict__ x,
        const float* __restrict__ Wg,
        const float* __restrict__ bg)
{
    const int warp = threadIdx.x >> 5;
    const int lane = threadIdx.x & 31;
    const int t = blockIdx.x * 8 + warp;
    if (t >= NTOK) return;

    const float4* x4 = reinterpret_cast<const float4*>(x) + (size_t)t * (HDIM / 4);
    const float4* w4 = reinterpret_cast<const float4*>(Wg);

    float acc[NEXP];
#pragma unroll
    for (int e = 0; e < NEXP; ++e) acc[e] = 0.f;

#pragma unroll
    for (int j = 0; j < 8; ++j) {
        const int i4 = lane + j * 32;          // 0..255 float4 chunks of the row
        const float4 xv = x4[i4];
#pragma unroll
        for (int e = 0; e < NEXP; ++e) {
            const float4 wv = w4[e * (HDIM / 4) + i4];
            acc[e] = fmaf(xv.x, wv.x, acc[e]);
            acc[e] = fmaf(xv.y, wv.y, acc[e]);
            acc[e] = fmaf(xv.z, wv.z, acc[e]);
            acc[e] = fmaf(xv.w, wv.w, acc[e]);
        }
    }
#pragma unroll
    for (int e = 0; e < NEXP; ++e) {
#pragma unroll
        for (int off = 16; off > 0; off >>= 1)
            acc[e] += __shfl_xor_sync(0xffffffffu, acc[e], off);
    }

    if (lane == 0) {
        float l[NEXP];
#pragma unroll
        for (int e = 0; e < NEXP; ++e) l[e] = acc[e] + bg[e];

        // top-2 with lowest-index tie-break (matches jax.lax.top_k)
        int e0 = 0;
#pragma unroll
        for (int e = 1; e < NEXP; ++e) if (l[e] > l[e0]) e0 = e;
        int e1 = (e0 == 0) ? 1 : 0;
#pragma unroll
        for (int e = 0; e < NEXP; ++e) {
            if (e == e0) continue;
            if (l[e] > l[e1]) e1 = e;
        }
        // renormalized top-2 softmax == 2-way softmax over the top-2 logits
        const float d  = expf(l[e1] - l[e0]);   // <= 1, no overflow
        const float s  = 1.f / (1.f + d);
        const float w0 = s;
        const float w1 = d * s;

        int p0 = atomicAdd(&g_cnt[e0], 1);
        g_tok[e0][p0] = t; g_wt[e0][p0] = w0;
        int p1 = atomicAdd(&g_cnt[e1], 1);
        g_tok[e1][p1] = t; g_wt[e1][p1] = w1;
    }
}

// Grouped GEMM: for expert e, out[tok, h] += w_tok * ( x[tok,:] . W[h*E+e,:] + b[h*E+e] )
// Tile 64x64, K-chunk 16, 256 threads, 4x4 microtile. x rows pre-scaled by w_tok.
__global__ __launch_bounds__(256) void moe_gemm_kernel(
        const float* __restrict__ x,
        const float* __restrict__ We,
        const float* __restrict__ be,
        float* __restrict__ out)
{
    const int e   = blockIdx.z;
    const int cnt = g_cnt[e];
    const int m0  = blockIdx.x * BM;
    if (m0 >= cnt) return;
    const int h0  = blockIdx.y * BN;

    __shared__ float As[BK][BM + 4];
    __shared__ float Bs[BK][BN + 4];

    const int tid = threadIdx.x;
    const int lr  = tid >> 2;            // tile row this thread loads (0..63)
    const int lk  = (tid & 3) << 2;      // k offset within chunk (0,4,8,12)

    // A-side (gathered, weight-scaled) row for the load phase
    const int am = m0 + lr;
    float aw  = 0.f;
    int atok  = 0;
    if (am < cnt) { atok = g_tok[e][am]; aw = g_wt[e][am]; }
    const float* aptr = x + (size_t)atok * HDIM + lk;
    // B-side row: expert e's h-th row lives at W_experts[(h*E + e), :]
    const float* bptr = We + ((size_t)(h0 + lr) * NEXP + e) * HDIM + lk;

    const int tx = tid & 15;
    const int ty = tid >> 4;

    float c[4][4];
#pragma unroll
    for (int i = 0; i < 4; ++i)
#pragma unroll
        for (int j = 0; j < 4; ++j) c[i][j] = 0.f;

    for (int k0 = 0; k0 < HDIM; k0 += BK) {
        float4 av = *reinterpret_cast<const float4*>(aptr + k0);
        float4 bv = *reinterpret_cast<const float4*>(bptr + k0);
        av.x *= aw; av.y *= aw; av.z *= aw; av.w *= aw;
        As[lk + 0][lr] = av.x; As[lk + 1][lr] = av.y;
        As[lk + 2][lr] = av.z; As[lk + 3][lr] = av.w;
        Bs[lk + 0][lr] = bv.x; Bs[lk + 1][lr] = bv.y;
        Bs[lk + 2][lr] = bv.z; Bs[lk + 3][lr] = bv.w;
        __syncthreads();

#pragma unroll
        for (int kk = 0; kk < BK; ++kk) {
            const float4 a4 = *reinterpret_cast<const float4*>(&As[kk][ty << 2]);
            const float4 b4 = *reinterpret_cast<const float4*>(&Bs[kk][tx << 2]);
            const float a[4] = {a4.x, a4.y, a4.z, a4.w};
            const float b[4] = {b4.x, b4.y, b4.z, b4.w};
#pragma unroll
            for (int i = 0; i < 4; ++i)
#pragma unroll
                for (int j = 0; j < 4; ++j)
                    c[i][j] = fmaf(a[i], b[j], c[i][j]);
        }
        __syncthreads();
    }

    // Epilogue: add weighted bias, atomically accumulate the 2 expert contributions.
#pragma unroll
    for (int i = 0; i < 4; ++i) {
        const int m = m0 + (ty << 2) + i;
        if (m >= cnt) continue;
        const int   tokn = g_tok[e][m];
        const float w    = g_wt[e][m];
        float* orow = out + (size_t)tokn * HDIM;
#pragma unroll
        for (int j = 0; j < 4; ++j) {
            const int h = h0 + (tx << 2) + j;
            atomicAdd(&orow[h], c[i][j] + w * be[h * NEXP + e]);
        }
    }
}

extern "C" void kernel_launch(void* const* d_in, const int* in_sizes, int n_in,
                              void* d_out, int out_size)
{
    const float* x  = (const float*)d_in[0];   // [8192, 1024]
    const float* We = (const float*)d_in[1];   // [8192, 1024]  (rows = h*E + e)
    const float* be = (const float*)d_in[2];   // [8192]
    const float* Wg = (const float*)d_in[3];   // [8, 1024]
    const float* bg = (const float*)d_in[4];   // [8]
    float* out = (float*)d_out;                // [8192, 1024]

    cudaMemsetAsync(out, 0, (size_t)out_size * sizeof(float));
    zero_counts_kernel<<<1, 32>>>();
    gate_kernel<<<NTOK / 8, 256>>>(x, Wg, bg);

    dim3 grid(NTOK / BM, HDIM / BN, NEXP);
    moe_gemm_kernel<<<grid, 256>>>(x, We, be, out);
}

// round 2
// speedup vs baseline: 3.0967x; 3.0967x over previous
#include <cuda_runtime.h>
#include <cstdint>

// Sparse MoE FFN: T=8192 tokens, H=1024 hidden, E=8 experts, top-2 routing.
// out[t,h] = sum_{k in top2(t)} w_k * ( x[t,:] . W_experts[h*E+e_k, :] + b_experts[h*E+e_k] )

#define NTOK 8192
#define HDIM 1024
#define NEXP 8

#define BM 128
#define BN 128
#define BK 16
#define NKITER (HDIM / BK)      // 64
#define SSTRIDE (BK + 4)        // 20 floats: conflict-free for mma fragment reads

// Routing scratch.
__device__ int   g_cnt[NEXP];
__device__ int   g_tok[NEXP][NTOK];
__device__ float g_wt [NEXP][NTOK];

__global__ void zero_counts_kernel() {
    if (threadIdx.x < NEXP) g_cnt[threadIdx.x] = 0;
}

// One warp per token: 8 gate logits, top-2, renormalized weights, per-expert lists.
__global__ __launch_bounds__(256) void gate_kernel(
        const float* __restrict__ x,
        const float* __restrict__ Wg,
        const float* __restrict__ bg)
{
    const int warp = threadIdx.x >> 5;
    const int lane = threadIdx.x & 31;
    const int t = blockIdx.x * 8 + warp;
    if (t >= NTOK) return;

    const float4* x4 = reinterpret_cast<const float4*>(x) + (size_t)t * (HDIM / 4);
    const float4* w4 = reinterpret_cast<const float4*>(Wg);

    float acc[NEXP];
#pragma unroll
    for (int e = 0; e < NEXP; ++e) acc[e] = 0.f;

#pragma unroll
    for (int j = 0; j < 8; ++j) {
        const int i4 = lane + j * 32;
        const float4 xv = x4[i4];
#pragma unroll
        for (int e = 0; e < NEXP; ++e) {
            const float4 wv = w4[e * (HDIM / 4) + i4];
            acc[e] = fmaf(xv.x, wv.x, acc[e]);
            acc[e] = fmaf(xv.y, wv.y, acc[e]);
            acc[e] = fmaf(xv.z, wv.z, acc[e]);
            acc[e] = fmaf(xv.w, wv.w, acc[e]);
        }
    }
#pragma unroll
    for (int e = 0; e < NEXP; ++e) {
#pragma unroll
        for (int off = 16; off > 0; off >>= 1)
            acc[e] += __shfl_xor_sync(0xffffffffu, acc[e], off);
    }

    if (lane == 0) {
        float l[NEXP];
#pragma unroll
        for (int e = 0; e < NEXP; ++e) l[e] = acc[e] + bg[e];

        int e0 = 0;
#pragma unroll
        for (int e = 1; e < NEXP; ++e) if (l[e] > l[e0]) e0 = e;
        int e1 = (e0 == 0) ? 1 : 0;
#pragma unroll
        for (int e = 0; e < NEXP; ++e) {
            if (e == e0) continue;
            if (l[e] > l[e1]) e1 = e;
        }
        const float d  = expf(l[e1] - l[e0]);
        const float s  = 1.f / (1.f + d);

        int p0 = atomicAdd(&g_cnt[e0], 1);
        g_tok[e0][p0] = t; g_wt[e0][p0] = s;
        int p1 = atomicAdd(&g_cnt[e1], 1);
        g_tok[e1][p1] = t; g_wt[e1][p1] = d * s;
    }
}

__device__ __forceinline__ void cpasync16(void* dst, const void* src) {
    unsigned d = (unsigned)__cvta_generic_to_shared(dst);
    asm volatile("cp.async.cg.shared.global [%0], [%1], 16;" :: "r"(d), "l"(src));
}
__device__ __forceinline__ uint32_t f2tf(float f) {
    uint32_t u;
    asm("cvt.rna.tf32.f32 %0, %1;" : "=r"(u) : "f"(f));
    return u;
}
__device__ __forceinline__ void mma_tf32(float* c, const uint32_t* a, const uint32_t* b) {
    asm volatile(
        "mma.sync.aligned.m16n8k8.row.col.f32.tf32.tf32.f32 "
        "{%0,%1,%2,%3}, {%4,%5,%6,%7}, {%8,%9}, {%0,%1,%2,%3};"
        : "+f"(c[0]), "+f"(c[1]), "+f"(c[2]), "+f"(c[3])
        : "r"(a[0]), "r"(a[1]), "r"(a[2]), "r"(a[3]), "r"(b[0]), "r"(b[1]));
}

// Grouped GEMM on tensor cores (tf32). C = Xg[BM,1024] @ We_e[1024,BN]^T (raw rows),
// epilogue applies per-token gate weight and weighted bias via vector red.
__global__ __launch_bounds__(256, 2) void moe_gemm_tc(
        const float* __restrict__ x,
        const float* __restrict__ We,
        const float* __restrict__ be,
        float* __restrict__ out)
{
    const int e   = blockIdx.z;
    const int cnt = g_cnt[e];
    const int m0  = blockIdx.x * BM;
    if (m0 >= cnt) return;
    const int h0  = blockIdx.y * BN;

    __shared__ float sA[2][BM][SSTRIDE];
    __shared__ float sB[2][BN][SSTRIDE];

    const int tid  = threadIdx.x;
    const int wid  = tid >> 5;
    const int lane = tid & 31;
    const int wm   = (wid & 1) * 64;   // warp m-origin in tile
    const int wn   = (wid >> 1) * 32;  // warp n-origin
    const int g    = lane >> 2;        // 0..7
    const int t4   = lane & 3;         // 0..3

    // GMEM->SMEM load mapping: thread loads rows (tid>>2, tid>>2+64), 16B at koff.
    const int lr = tid >> 2;           // 0..63
    const int lk = (tid & 3) * 4;      // float offset 0,4,8,12
    const int r0 = min(m0 + lr,      cnt - 1);
    const int r1 = min(m0 + lr + 64, cnt - 1);
    const float* aptr0 = x + (size_t)g_tok[e][r0] * HDIM + lk;
    const float* aptr1 = x + (size_t)g_tok[e][r1] * HDIM + lk;
    const float* bptr0 = We + ((size_t)(h0 + lr)      * NEXP + e) * HDIM + lk;
    const float* bptr1 = We + ((size_t)(h0 + lr + 64) * NEXP + e) * HDIM + lk;

    float c[4][4][4];
#pragma unroll
    for (int i = 0; i < 4; ++i)
#pragma unroll
        for (int j = 0; j < 4; ++j)
#pragma unroll
            for (int q = 0; q < 4; ++q) c[i][j][q] = 0.f;

    // Prologue: stage 0
    cpasync16(&sA[0][lr][lk],      aptr0);
    cpasync16(&sA[0][lr + 64][lk], aptr1);
    cpasync16(&sB[0][lr][lk],      bptr0);
    cpasync16(&sB[0][lr + 64][lk], bptr1);
    asm volatile("cp.async.commit_group;");

    for (int kt = 0; kt < NKITER; ++kt) {
        const int s = kt & 1;
        if (kt + 1 < NKITER) {
            const int ns = s ^ 1;
            const int k  = (kt + 1) * BK;
            cpasync16(&sA[ns][lr][lk],      aptr0 + k);
            cpasync16(&sA[ns][lr + 64][lk], aptr1 + k);
            cpasync16(&sB[ns][lr][lk],      bptr0 + k);
            cpasync16(&sB[ns][lr + 64][lk], bptr1 + k);
            asm volatile("cp.async.commit_group;");
            asm volatile("cp.async.wait_group 1;" ::: "memory");
        } else {
            asm volatile("cp.async.wait_group 0;" ::: "memory");
        }
        __syncthreads();

#pragma unroll
        for (int ks = 0; ks < 2; ++ks) {
            const int kb = ks * 8;
            uint32_t a[4][4], b[4][2];
#pragma unroll
            for (int mc = 0; mc < 4; ++mc) {
                const int row = wm + mc * 16 + g;
                a[mc][0] = f2tf(sA[s][row]    [kb + t4]);
                a[mc][1] = f2tf(sA[s][row + 8][kb + t4]);
                a[mc][2] = f2tf(sA[s][row]    [kb + t4 + 4]);
                a[mc][3] = f2tf(sA[s][row + 8][kb + t4 + 4]);
            }
#pragma unroll
            for (int nc = 0; nc < 4; ++nc) {
                const int n = wn + nc * 8 + g;
                b[nc][0] = f2tf(sB[s][n][kb + t4]);
                b[nc][1] = f2tf(sB[s][n][kb + t4 + 4]);
            }
#pragma unroll
            for (int mc = 0; mc < 4; ++mc)
#pragma unroll
                for (int nc = 0; nc < 4; ++nc)
                    mma_tf32(c[mc][nc], a[mc], b[nc]);
        }
        __syncthreads();
    }

    // Epilogue: out[tok,h] += w * (c + bias[h*E+e]) via 64-bit vector reductions.
#pragma unroll
    for (int mc = 0; mc < 4; ++mc) {
#pragma unroll
        for (int half = 0; half < 2; ++half) {
            const int rrel = wm + mc * 16 + g + half * 8;
            const int m    = m0 + rrel;
            if (m >= cnt) continue;
            const int   tok = g_tok[e][m];
            const float w   = g_wt[e][m];
            float* orow = out + (size_t)tok * HDIM;
#pragma unroll
            for (int nc = 0; nc < 4; ++nc) {
                const int h  = h0 + wn + nc * 8 + t4 * 2;
                const float v0 = w * (c[mc][nc][half * 2 + 0] + be[(h + 0) * NEXP + e]);
                const float v1 = w * (c[mc][nc][half * 2 + 1] + be[(h + 1) * NEXP + e]);
                asm volatile("red.global.add.v2.f32 [%0], {%1,%2};"
                             :: "l"(orow + h), "f"(v0), "f"(v1) : "memory");
            }
        }
    }
}

extern "C" void kernel_launch(void* const* d_in, const int* in_sizes, int n_in,
                              void* d_out, int out_size)
{
    const float* x  = (const float*)d_in[0];   // [8192, 1024]
    const float* We = (const float*)d_in[1];   // [8192, 1024] rows = h*E + e
    const float* be = (const float*)d_in[2];   // [8192]
    const float* Wg = (const float*)d_in[3];   // [8, 1024]
    const float* bg = (const float*)d_in[4];   // [8]
    float* out = (float*)d_out;                // [8192, 1024]

    cudaMemsetAsync(out, 0, (size_t)out_size * sizeof(float));
    zero_counts_kernel<<<1, 32>>>();
    gate_kernel<<<NTOK / 8, 256>>>(x, Wg, bg);

    dim3 grid(NTOK / BM, HDIM / BN, NEXP);   // worst-case m-tiles; inactive exit fast
    moe_gemm_tc<<<grid, 256>>>(x, We, be, out);
}

// round 6
// speedup vs baseline: 4.5379x; 1.4654x over previous
#include <cuda_runtime.h>
#include <cuda_fp16.h>
#include <cstdint>

// Sparse MoE FFN: T=8192 tokens, H=1024, E=8 experts, top-2 routing.
// Legacy tensor-core path (sm_100 plain target): fp16 mma m16n8k16, fp32 accum.

#define NTOK 8192
#define HDIM 1024
#define NEXP 8

#define BM 128
#define BN 128
#define BK 32                   // halves per k-chunk
#define NC (HDIM / BK)          // 32 chunks
#define STAGES 3
#define ROWH 40                 // padded row stride in halves (80 B) -> conflict-free frags
#define TILEH (BM * ROWH)       // halves per (A or B) stage tile
#define SMEM_BYTES (STAGES * 2 * TILEH * 2)   // 61440 B

// Routing + half scratch (device globals; no allocs allowed).
__device__ int    g_cnt[NEXP];
__device__ int    g_tok[NEXP][NTOK];
__device__ float  g_gw [NEXP][NTOK];
__device__ __half g_xh [NTOK * HDIM];    // x as fp16
__device__ __half g_weh[NTOK * HDIM];    // W_experts as fp16

// Pack two fp32 -> one fp16x2 register (rn rounding).
__device__ __forceinline__ uint32_t pack_h2(float lo, float hi) {
    uint32_t r;
    asm("cvt.rn.f16x2.f32 %0, %1, %2;" : "=r"(r) : "f"(hi), "f"(lo));
    return r;
}

__global__ void zero_counts_kernel() {
    if (threadIdx.x < NEXP) g_cnt[threadIdx.x] = 0;
}

// One warp per token: gate logits (fp32), top-2, renorm weights; fused x->fp16.
__global__ __launch_bounds__(256) void gate_kernel(
        const float* __restrict__ x,
        const float* __restrict__ Wg,
        const float* __restrict__ bg)
{
    const int warp = threadIdx.x >> 5;
    const int lane = threadIdx.x & 31;
    const int t = blockIdx.x * 8 + warp;
    if (t >= NTOK) return;

    const float4* x4 = reinterpret_cast<const float4*>(x) + (size_t)t * (HDIM / 4);
    const float4* w4 = reinterpret_cast<const float4*>(Wg);
    uint2* xo = reinterpret_cast<uint2*>(g_xh) + (size_t)t * (HDIM / 4);

    float acc[NEXP];
#pragma unroll
    for (int e = 0; e < NEXP; ++e) acc[e] = 0.f;

#pragma unroll
    for (int j = 0; j < 8; ++j) {
        const int i4 = lane + j * 32;
        const float4 xv = x4[i4];
        uint2 o;
        o.x = pack_h2(xv.x, xv.y);
        o.y = pack_h2(xv.z, xv.w);
        xo[i4] = o;
#pragma unroll
        for (int e = 0; e < NEXP; ++e) {
            const float4 wv = w4[e * (HDIM / 4) + i4];
            acc[e] = fmaf(xv.x, wv.x, acc[e]);
            acc[e] = fmaf(xv.y, wv.y, acc[e]);
            acc[e] = fmaf(xv.z, wv.z, acc[e]);
            acc[e] = fmaf(xv.w, wv.w, acc[e]);
        }
    }
#pragma unroll
    for (int e = 0; e < NEXP; ++e) {
#pragma unroll
        for (int off = 16; off > 0; off >>= 1)
            acc[e] += __shfl_xor_sync(0xffffffffu, acc[e], off);
    }

    if (lane == 0) {
        float l[NEXP];
#pragma unroll
        for (int e = 0; e < NEXP; ++e) l[e] = acc[e] + bg[e];
        int e0 = 0;
#pragma unroll
        for (int e = 1; e < NEXP; ++e) if (l[e] > l[e0]) e0 = e;
        int e1 = (e0 == 0) ? 1 : 0;
#pragma unroll
        for (int e = 0; e < NEXP; ++e) {
            if (e == e0) continue;
            if (l[e] > l[e1]) e1 = e;
        }
        const float d = expf(l[e1] - l[e0]);
        const float s = 1.f / (1.f + d);
        int p0 = atomicAdd(&g_cnt[e0], 1);
        g_tok[e0][p0] = t; g_gw[e0][p0] = s;
        int p1 = atomicAdd(&g_cnt[e1], 1);
        g_tok[e1][p1] = t; g_gw[e1][p1] = d * s;
    }
}

__global__ __launch_bounds__(256) void conv_we_kernel(const float* __restrict__ We) {
    const float4* src = reinterpret_cast<const float4*>(We);
    uint2* dst = reinterpret_cast<uint2*>(g_weh);
    const int n = NTOK * HDIM / 4;
    for (int i = blockIdx.x * blockDim.x + threadIdx.x; i < n; i += gridDim.x * blockDim.x) {
        const float4 v = src[i];
        uint2 o;
        o.x = pack_h2(v.x, v.y);
        o.y = pack_h2(v.z, v.w);
        dst[i] = o;
    }
}

__device__ __forceinline__ void cpasync16(void* dst, const void* src) {
    unsigned d = (unsigned)__cvta_generic_to_shared(dst);
    asm volatile("cp.async.cg.shared.global [%0], [%1], 16;" :: "r"(d), "l"(src));
}

__device__ __forceinline__ void mma_f16(float* c, const uint32_t* a, const uint32_t* b) {
    asm volatile(
        "mma.sync.aligned.m16n8k16.row.col.f32.f16.f16.f32 "
        "{%0,%1,%2,%3}, {%4,%5,%6,%7}, {%8,%9}, {%0,%1,%2,%3};"
        : "+f"(c[0]), "+f"(c[1]), "+f"(c[2]), "+f"(c[3])
        : "r"(a[0]), "r"(a[1]), "r"(a[2]), "r"(a[3]), "r"(b[0]), "r"(b[1]));
}

// Grouped GEMM: expert e, tile [m0:m0+128) x [h0:h0+128), K=1024, fp16 inputs.
// Dynamic smem: [STAGES][A tile | B tile], each tile BM*ROWH halves.
__global__ __launch_bounds__(256) void moe_gemm_f16(
        const float* __restrict__ be,
        float* __restrict__ out)
{
    const int e   = blockIdx.z;
    const int cnt = g_cnt[e];
    const int m0  = blockIdx.x * BM;
    if (m0 >= cnt) return;
    const int h0  = blockIdx.y * BN;

    extern __shared__ __half smem[];
    __half* sA[STAGES];
    __half* sB[STAGES];
#pragma unroll
    for (int s = 0; s < STAGES; ++s) {
        sA[s] = smem + s * 2 * TILEH;
        sB[s] = smem + s * 2 * TILEH + TILEH;
    }

    const int tid  = threadIdx.x;
    const int wid  = tid >> 5;
    const int lane = tid & 31;
    const int wm   = (wid & 1) * 64;
    const int wn   = (wid >> 1) * 32;
    const int g    = lane >> 2;
    const int t4   = lane & 3;

    // GMEM->SMEM: each thread loads 2 rows x one 16B chunk (8 halves).
    const int lrow = tid >> 2;          // 0..63
    const int lch  = (tid & 3) * 8;     // half offset within chunk row: 0,8,16,24
    const int r0 = min(m0 + lrow,      cnt - 1);
    const int r1 = min(m0 + lrow + 64, cnt - 1);
    const __half* aptr0 = g_xh + (size_t)g_tok[e][r0] * HDIM + lch;
    const __half* aptr1 = g_xh + (size_t)g_tok[e][r1] * HDIM + lch;
    const __half* bptr0 = g_weh + ((size_t)(h0 + lrow)      * NEXP + e) * HDIM + lch;
    const __half* bptr1 = g_weh + ((size_t)(h0 + lrow + 64) * NEXP + e) * HDIM + lch;
    const int sd0 = lrow * ROWH + lch;
    const int sd1 = (lrow + 64) * ROWH + lch;

    float c[4][4][4];
#pragma unroll
    for (int i = 0; i < 4; ++i)
#pragma unroll
        for (int j = 0; j < 4; ++j)
#pragma unroll
            for (int q = 0; q < 4; ++q) c[i][j][q] = 0.f;

    // Prologue: stages 0..STAGES-2
#pragma unroll
    for (int cpre = 0; cpre < STAGES - 1; ++cpre) {
        const int k = cpre * BK;
        cpasync16(&sA[cpre][sd0], aptr0 + k);
        cpasync16(&sA[cpre][sd1], aptr1 + k);
        cpasync16(&sB[cpre][sd0], bptr0 + k);
        cpasync16(&sB[cpre][sd1], bptr1 + k);
        asm volatile("cp.async.commit_group;");
    }

    for (int ck = 0; ck < NC; ++ck) {
        const int s = ck % STAGES;
        const int cl = ck + STAGES - 1;
        if (cl < NC) {
            const int ns = cl % STAGES;
            const int k  = cl * BK;
            cpasync16(&sA[ns][sd0], aptr0 + k);
            cpasync16(&sA[ns][sd1], aptr1 + k);
            cpasync16(&sB[ns][sd0], bptr0 + k);
            cpasync16(&sB[ns][sd1], bptr1 + k);
            asm volatile("cp.async.commit_group;");
            asm volatile("cp.async.wait_group %0;" :: "n"(STAGES - 1) : "memory");
        } else {
            asm volatile("cp.async.wait_group 0;" ::: "memory");
        }
        __syncthreads();

#pragma unroll
        for (int ks = 0; ks < 2; ++ks) {
            const int kb = ks * 16 + t4 * 2;
            uint32_t a[4][4], b[4][2];
#pragma unroll
            for (int mc = 0; mc < 4; ++mc) {
                const int row = wm + mc * 16 + g;
                a[mc][0] = *reinterpret_cast<const uint32_t*>(&sA[s][row * ROWH + kb]);
                a[mc][1] = *reinterpret_cast<const uint32_t*>(&sA[s][(row + 8) * ROWH + kb]);
                a[mc][2] = *reinterpret_cast<const uint32_t*>(&sA[s][row * ROWH + kb + 8]);
                a[mc][3] = *reinterpret_cast<const uint32_t*>(&sA[s][(row + 8) * ROWH + kb + 8]);
            }
#pragma unroll
            for (int nc = 0; nc < 4; ++nc) {
                const int n = wn + nc * 8 + g;
                b[nc][0] = *reinterpret_cast<const uint32_t*>(&sB[s][n * ROWH + kb]);
                b[nc][1] = *reinterpret_cast<const uint32_t*>(&sB[s][n * ROWH + kb + 8]);
            }
#pragma unroll
            for (int mc = 0; mc < 4; ++mc)
#pragma unroll
                for (int nc = 0; nc < 4; ++nc)
                    mma_f16(c[mc][nc], a[mc], b[nc]);
        }
        __syncthreads();
    }

    // Epilogue: out[tok,h] += w * (c + bias[h*E+e]) via 64-bit vector reductions.
#pragma unroll
    for (int mc = 0; mc < 4; ++mc) {
#pragma unroll
        for (int half = 0; half < 2; ++half) {
            const int rrel = wm + mc * 16 + g + half * 8;
            const int m    = m0 + rrel;
            if (m >= cnt) continue;
            const int   tok = g_tok[e][m];
            const float w   = g_gw[e][m];
            float* orow = out + (size_t)tok * HDIM;
#pragma unroll
            for (int nc = 0; nc < 4; ++nc) {
                const int h  = h0 + wn + nc * 8 + t4 * 2;
                const float v0 = w * (c[mc][nc][half * 2 + 0] + be[(h + 0) * NEXP + e]);
                const float v1 = w * (c[mc][nc][half * 2 + 1] + be[(h + 1) * NEXP + e]);
                asm volatile("red.global.add.v2.f32 [%0], {%1,%2};"
                             :: "l"(orow + h), "f"(v0), "f"(v1) : "memory");
            }
        }
    }
}

extern "C" void kernel_launch(void* const* d_in, const int* in_sizes, int n_in,
                              void* d_out, int out_size)
{
    const float* x  = (const float*)d_in[0];   // [8192, 1024]
    const float* We = (const float*)d_in[1];   // [8192, 1024] rows = h*E + e
    const float* be = (const float*)d_in[2];   // [8192]
    const float* Wg = (const float*)d_in[3];   // [8, 1024]
    const float* bg = (const float*)d_in[4];   // [8]
    float* out = (float*)d_out;                // [8192, 1024]

    static bool attr_set = false;
    if (!attr_set) {
        cudaFuncSetAttribute(moe_gemm_f16,
                             cudaFuncAttributeMaxDynamicSharedMemorySize, SMEM_BYTES);
        attr_set = true;
    }

    cudaMemsetAsync(out, 0, (size_t)out_size * sizeof(float));
    zero_counts_kernel<<<1, 32>>>();
    gate_kernel<<<NTOK / 8, 256>>>(x, Wg, bg);
    conv_we_kernel<<<512, 256>>>(We);

    dim3 grid(NTOK / BM, HDIM / BN, NEXP);   // worst-case m-tiles; inactive exit fast
    moe_gemm_f16<<<grid, 256, SMEM_BYTES>>>(be, out);
}

// round 7
// speedup vs baseline: 5.1804x; 1.1416x over previous
#include <cuda_runtime.h>
#include <cuda_fp16.h>
#include <cstdint>

// Sparse MoE FFN: T=8192 tokens, H=1024, E=8 experts, top-2 routing.
// fp16 mma m16n8k16 (fp32 accum), ldmatrix fragment loads, 4-stage cp.async.

#define NTOK 8192
#define HDIM 1024
#define NEXP 8

#define BM 128
#define BN 128
#define BK 32                   // halves per k-chunk
#define NC (HDIM / BK)          // 32 chunks
#define STAGES 4
#define ROWH 40                 // padded row stride in halves (80 B) -> conflict-free
#define TILEH (BM * ROWH)       // halves per (A or B) stage tile
#define STAGEH (2 * TILEH)      // halves per stage (A + B)
#define SMEM_BYTES (STAGES * STAGEH * 2)   // 81920 B

// Routing + half scratch.
__device__ int    g_cnt[NEXP];
__device__ int    g_tok[NEXP][NTOK];
__device__ float  g_gw [NEXP][NTOK];
__device__ __half g_xh [NTOK * HDIM];
__device__ __half g_weh[NTOK * HDIM];

__device__ __forceinline__ uint32_t pack_h2(float lo, float hi) {
    uint32_t r;
    asm("cvt.rn.f16x2.f32 %0, %1, %2;" : "=r"(r) : "f"(hi), "f"(lo));
    return r;
}

// Fused: blocks [0,1024) gate+convert x; blocks [1024,1536) convert We.
__global__ __launch_bounds__(256) void gate_conv_kernel(
        const float* __restrict__ x,
        const float* __restrict__ Wg,
        const float* __restrict__ bg,
        const float* __restrict__ We)
{
    if (blockIdx.x >= NTOK / 8) {
        const int bid = blockIdx.x - NTOK / 8;
        const float4* src = reinterpret_cast<const float4*>(We);
        uint2* dst = reinterpret_cast<uint2*>(g_weh);
        const int n = NTOK * HDIM / 4;
        const int stride = 512 * 256;
        for (int i = bid * 256 + threadIdx.x; i < n; i += stride) {
            const float4 v = src[i];
            uint2 o;
            o.x = pack_h2(v.x, v.y);
            o.y = pack_h2(v.z, v.w);
            dst[i] = o;
        }
        return;
    }

    const int warp = threadIdx.x >> 5;
    const int lane = threadIdx.x & 31;
    const int t = blockIdx.x * 8 + warp;

    const float4* x4 = reinterpret_cast<const float4*>(x) + (size_t)t * (HDIM / 4);
    const float4* w4 = reinterpret_cast<const float4*>(Wg);
    uint2* xo = reinterpret_cast<uint2*>(g_xh) + (size_t)t * (HDIM / 4);

    float acc[NEXP];
#pragma unroll
    for (int e = 0; e < NEXP; ++e) acc[e] = 0.f;

#pragma unroll
    for (int j = 0; j < 8; ++j) {
        const int i4 = lane + j * 32;
        const float4 xv = x4[i4];
        uint2 o;
        o.x = pack_h2(xv.x, xv.y);
        o.y = pack_h2(xv.z, xv.w);
        xo[i4] = o;
#pragma unroll
        for (int e = 0; e < NEXP; ++e) {
            const float4 wv = w4[e * (HDIM / 4) + i4];
            acc[e] = fmaf(xv.x, wv.x, acc[e]);
            acc[e] = fmaf(xv.y, wv.y, acc[e]);
            acc[e] = fmaf(xv.z, wv.z, acc[e]);
            acc[e] = fmaf(xv.w, wv.w, acc[e]);
        }
    }
#pragma unroll
    for (int e = 0; e < NEXP; ++e) {
#pragma unroll
        for (int off = 16; off > 0; off >>= 1)
            acc[e] += __shfl_xor_sync(0xffffffffu, acc[e], off);
    }

    if (lane == 0) {
        float l[NEXP];
#pragma unroll
        for (int e = 0; e < NEXP; ++e) l[e] = acc[e] + bg[e];
        int e0 = 0;
#pragma unroll
        for (int e = 1; e < NEXP; ++e) if (l[e] > l[e0]) e0 = e;
        int e1 = (e0 == 0) ? 1 : 0;
#pragma unroll
        for (int e = 0; e < NEXP; ++e) {
            if (e == e0) continue;
            if (l[e] > l[e1]) e1 = e;
        }
        const float d = expf(l[e1] - l[e0]);
        const float s = 1.f / (1.f + d);
        int p0 = atomicAdd(&g_cnt[e0], 1);
        g_tok[e0][p0] = t; g_gw[e0][p0] = s;
        int p1 = atomicAdd(&g_cnt[e1], 1);
        g_tok[e1][p1] = t; g_gw[e1][p1] = d * s;
    }
}

__device__ __forceinline__ void cpasync16(void* dst, const void* src) {
    unsigned d = (unsigned)__cvta_generic_to_shared(dst);
    asm volatile("cp.async.cg.shared.global [%0], [%1], 16;" :: "r"(d), "l"(src));
}
__device__ __forceinline__ void ldsm_x4(uint32_t* r, uint32_t addr) {
    asm volatile("ldmatrix.sync.aligned.m8n8.x4.shared.b16 {%0,%1,%2,%3}, [%4];"
                 : "=r"(r[0]), "=r"(r[1]), "=r"(r[2]), "=r"(r[3]) : "r"(addr));
}
__device__ __forceinline__ void mma_f16(float* c, const uint32_t* a, const uint32_t* b) {
    asm volatile(
        "mma.sync.aligned.m16n8k16.row.col.f32.f16.f16.f32 "
        "{%0,%1,%2,%3}, {%4,%5,%6,%7}, {%8,%9}, {%0,%1,%2,%3};"
        : "+f"(c[0]), "+f"(c[1]), "+f"(c[2]), "+f"(c[3])
        : "r"(a[0]), "r"(a[1]), "r"(a[2]), "r"(a[3]), "r"(b[0]), "r"(b[1]));
}

// Grouped GEMM: expert e, tile [m0:m0+128) x [h0:h0+128), K=1024, fp16 inputs.
__global__ __launch_bounds__(256) void moe_gemm_f16(
        const float* __restrict__ be,
        float* __restrict__ out)
{
    const int e   = blockIdx.z;
    const int cnt = g_cnt[e];
    const int m0  = blockIdx.x * BM;
    if (m0 >= cnt) return;
    const int h0  = blockIdx.y * BN;

    extern __shared__ __half smem[];
    const uint32_t sbase = (uint32_t)__cvta_generic_to_shared(smem);

    const int tid  = threadIdx.x;
    const int wid  = tid >> 5;
    const int lane = tid & 31;
    const int wm   = (wid & 1) * 64;
    const int wn   = (wid >> 1) * 32;
    const int g    = lane >> 2;
    const int t4   = lane & 3;

    // GMEM->SMEM: each thread loads 2 rows x one 16B chunk (8 halves).
    const int lrow = tid >> 2;
    const int lch  = (tid & 3) * 8;
    const int r0 = min(m0 + lrow,      cnt - 1);
    const int r1 = min(m0 + lrow + 64, cnt - 1);
    const __half* aptr0 = g_xh + (size_t)g_tok[e][r0] * HDIM + lch;
    const __half* aptr1 = g_xh + (size_t)g_tok[e][r1] * HDIM + lch;
    const __half* bptr0 = g_weh + ((size_t)(h0 + lrow)      * NEXP + e) * HDIM + lch;
    const __half* bptr1 = g_weh + ((size_t)(h0 + lrow + 64) * NEXP + e) * HDIM + lch;
    const int sd0 = lrow * ROWH + lch;
    const int sd1 = (lrow + 64) * ROWH + lch;

    // ldmatrix lane-address bases (bytes, relative to stage A/B tile base).
    // A frag (16x16): row = wm + mc*16 + (lane&15), col = ks*16 + (lane>>4)*8
    const uint32_t a_lane = (uint32_t)(((wm + (lane & 15)) * ROWH + (lane >> 4) * 8) * 2);
    // B frag pair (two n8 frags): row = wn + p*16 + ((lane>>4)<<3) + (lane&7),
    //                             col = ks*16 + ((lane>>3)&1)*8
    const uint32_t b_lane = (uint32_t)(((wn + ((lane >> 4) << 3) + (lane & 7)) * ROWH
                                        + ((lane >> 3) & 1) * 8) * 2 + TILEH * 2);

    float c[4][4][4];
#pragma unroll
    for (int i = 0; i < 4; ++i)
#pragma unroll
        for (int j = 0; j < 4; ++j)
#pragma unroll
            for (int q = 0; q < 4; ++q) c[i][j][q] = 0.f;

    // Prologue: fill stages 0..STAGES-2
#pragma unroll
    for (int cpre = 0; cpre < STAGES - 1; ++cpre) {
        const int k = cpre * BK;
        __half* sA = smem + cpre * STAGEH;
        __half* sB = sA + TILEH;
        cpasync16(&sA[sd0], aptr0 + k);
        cpasync16(&sA[sd1], aptr1 + k);
        cpasync16(&sB[sd0], bptr0 + k);
        cpasync16(&sB[sd1], bptr1 + k);
        asm volatile("cp.async.commit_group;");
    }

    for (int ck = 0; ck < NC; ++ck) {
        const int s = ck % STAGES;
        const int cl = ck + STAGES - 1;
        if (cl < NC) {
            const int ns = cl % STAGES;
            const int k  = cl * BK;
            __half* sA = smem + ns * STAGEH;
            __half* sB = sA + TILEH;
            cpasync16(&sA[sd0], aptr0 + k);
            cpasync16(&sA[sd1], aptr1 + k);
            cpasync16(&sB[sd0], bptr0 + k);
            cpasync16(&sB[sd1], bptr1 + k);
            asm volatile("cp.async.commit_group;");
            asm volatile("cp.async.wait_group %0;" :: "n"(STAGES - 1) : "memory");
        } else {
            asm volatile("cp.async.wait_group 0;" ::: "memory");
        }
        __syncthreads();

        const uint32_t stg = sbase + (uint32_t)(s * STAGEH * 2);
#pragma unroll
        for (int ks = 0; ks < 2; ++ks) {
            uint32_t a[4][4], b[2][4];
            const uint32_t ko = (uint32_t)(ks * 32);   // 16 halves
#pragma unroll
            for (int mc = 0; mc < 4; ++mc)
                ldsm_x4(a[mc], stg + a_lane + (uint32_t)(mc * 16 * ROWH * 2) + ko);
#pragma unroll
            for (int p = 0; p < 2; ++p)
                ldsm_x4(b[p], stg + b_lane + (uint32_t)(p * 16 * ROWH * 2) + ko);
#pragma unroll
            for (int mc = 0; mc < 4; ++mc)
#pragma unroll
                for (int nc = 0; nc < 4; ++nc)
                    mma_f16(c[mc][nc], a[mc], &b[nc >> 1][(nc & 1) * 2]);
        }
        __syncthreads();
    }

    // Epilogue: out[tok,h] += w * (c + bias[h*E+e]) via 64-bit vector reductions.
#pragma unroll
    for (int mc = 0; mc < 4; ++mc) {
#pragma unroll
        for (int half = 0; half < 2; ++half) {
            const int rrel = wm + mc * 16 + g + half * 8;
            const int m    = m0 + rrel;
            if (m >= cnt) continue;
            const int   tok = g_tok[e][m];
            const float w   = g_gw[e][m];
            float* orow = out + (size_t)tok * HDIM;
#pragma unroll
            for (int nc = 0; nc < 4; ++nc) {
                const int h  = h0 + wn + nc * 8 + t4 * 2;
                const float v0 = w * (c[mc][nc][half * 2 + 0] + be[(h + 0) * NEXP + e]);
                const float v1 = w * (c[mc][nc][half * 2 + 1] + be[(h + 1) * NEXP + e]);
                asm volatile("red.global.add.v2.f32 [%0], {%1,%2};"
                             :: "l"(orow + h), "f"(v0), "f"(v1) : "memory");
            }
        }
    }
}

extern "C" void kernel_launch(void* const* d_in, const int* in_sizes, int n_in,
                              void* d_out, int out_size)
{
    const float* x  = (const float*)d_in[0];
    const float* We = (const float*)d_in[1];
    const float* be = (const float*)d_in[2];
    const float* Wg = (const float*)d_in[3];
    const float* bg = (const float*)d_in[4];
    float* out = (float*)d_out;

    cudaFuncSetAttribute(moe_gemm_f16,
                         cudaFuncAttributeMaxDynamicSharedMemorySize, SMEM_BYTES);

    void* cntp = nullptr;
    cudaGetSymbolAddress(&cntp, g_cnt);
    cudaMemsetAsync(cntp, 0, NEXP * sizeof(int));
    cudaMemsetAsync(out, 0, (size_t)out_size * sizeof(float));

    gate_conv_kernel<<<NTOK / 8 + 512, 256>>>(x, Wg, bg, We);

    dim3 grid(NTOK / BM, HDIM / BN, NEXP);
    moe_gemm_f16<<<grid, 256, SMEM_BYTES>>>(be, out);
}